// round 9
// baseline (speedup 1.0000x reference)
#include <cuda_runtime.h>
#include <cstdint>

// Problem constants (fixed shapes)
#define BQ   4
#define KC   24
#define DD   16
#define NPIX (512 * 1024)
#define KP   17

// k_accum tiling
#define TILE        128
#define QROW        17
#define TILES_IMG   (NPIX / TILE)         // 4096 tiles per image
#define ABLK_X      185                   // 740 blocks total ≈ 5/SM one wave

#define CNT_BLKS    16

// ---------------- device scratch ----------------
__device__ float g_sums[BQ * KC * DD];
__device__ int   g_cnt_part[BQ * CNT_BLKS * KC];
__device__ float g_counts[BQ * KC];
__device__ float g_centers[BQ * KC * DD];
__device__ float g_invc[BQ * KC];
__device__ float g_vtot;
__device__ float g_extra;
__device__ unsigned int g_done;

// ---------------- pass 0: label histogram + zero g_sums ----------------
__global__ void __launch_bounds__(256) k_count(const int* __restrict__ labels) {
    __shared__ int s_h[8][KC + 8];
    const int t = threadIdx.x;
    const int w = t >> 5;
    const int b = blockIdx.y;
    const int* lptr = labels + (size_t)b * NPIX;

    if (blockIdx.x == 0 && b == 0) {
        for (int i = t; i < BQ * KC * DD; i += 256) g_sums[i] = 0.f;
    }

    for (int i = t; i < 8 * (KC + 8); i += 256)
        (&s_h[0][0])[i] = 0;
    __syncthreads();

    const int base = blockIdx.x * (256 * 32);
#pragma unroll 4
    for (int i = 0; i < 32; i++) {
        const int4 l4 = reinterpret_cast<const int4*>(lptr)[base + i * 256 + t];
        atomicAdd(&s_h[w][l4.x], 1);
        atomicAdd(&s_h[w][l4.y], 1);
        atomicAdd(&s_h[w][l4.z], 1);
        atomicAdd(&s_h[w][l4.w], 1);
    }
    __syncthreads();

    if (t < KC) {
        int s = 0;
#pragma unroll
        for (int c = 0; c < 8; c++) s += s_h[c][t];
        g_cnt_part[(b * CNT_BLKS + blockIdx.x) * KC + t] = s;
    }
}

// ---------------- pass 1: pipelined half-warp smem RMW ----------------
// TILE=128, double-buffered s_data, register prefetch of next tile (8 regs),
// one barrier per tile. Conflict-free rotated staging (proven R7 layout).
__global__ void __launch_bounds__(256) k_accum(const float* __restrict__ data,
                                               const int*  __restrict__ labels) {
    __shared__ float s_data[2][TILE * QROW];       // 2 x 8704 B
    __shared__ float s_acc[8 * 2 * KC * DD];       // 24576 B

    const int t = threadIdx.x;
    const int w = t >> 5;
    const int lane = t & 31;
    const int half = lane >> 4;
    const int dlane = lane & 15;

    const int b = blockIdx.y;
    const float* dptr = data + (size_t)b * DD * NPIX;
    const int*   lptr = labels + (size_t)b * NPIX;

    for (int i = t; i < 8 * 2 * KC * DD; i += 256) s_acc[i] = 0.f;

    // staging indices: 2 float4 per thread. idx in [0,512): d=idx>>5, pv=idx&31
    const int d0  = t >> 5,        pv0 = t & 31;
    const int d1  = (t + 256) >> 5, pv1 = t & 31;
    const int dd0 = (d0 + (pv0 >> 3)) & 15;        // rot = (q>>5)&3 = pv>>3
    const int dd1 = (d1 + (pv1 >> 3)) & 15;

    // gather-side: warp w owns points w*16 .. w*16+15; rot const = (w>>1)&3
    const int drot = (dlane + ((w >> 1) & 3)) & 15;
    const float* grow0 = &s_data[0][(w * 16 + half) * QROW + drot];
    const float* grow1 = &s_data[1][(w * 16 + half) * QROW + drot];
    float* accb = &s_acc[((w * 2 + half) * KC) * DD + dlane];

    // ---- prologue: stage tile bx into buf 0 ----
    int tile = blockIdx.x;
    {
        const int p4b = tile * (TILE / 4);
        const float4 v0 = reinterpret_cast<const float4*>(dptr + (size_t)d0 * NPIX)[p4b + pv0];
        const float4 v1 = reinterpret_cast<const float4*>(dptr + (size_t)d1 * NPIX)[p4b + pv1];
        float* r0 = &s_data[0][(pv0 * 4) * QROW + dd0];
        r0[0 * QROW] = v0.x; r0[1 * QROW] = v0.y; r0[2 * QROW] = v0.z; r0[3 * QROW] = v0.w;
        float* r1 = &s_data[0][(pv1 * 4) * QROW + dd1];
        r1[0 * QROW] = v1.x; r1[1 * QROW] = v1.y; r1[2 * QROW] = v1.z; r1[3 * QROW] = v1.w;
    }
    int labReg = lptr[tile * TILE + w * 16 + (lane & 15)];
    __syncthreads();

    int p = 0;
    while (true) {
        const int ntile = tile + ABLK_X;
        const bool more = (ntile < TILES_IMG);

        // ---- prefetch next tile into registers (latency hidden by gather) ----
        float4 r0, r1; int nlab = 0;
        if (more) {
            const int p4b = ntile * (TILE / 4);
            r0 = reinterpret_cast<const float4*>(dptr + (size_t)d0 * NPIX)[p4b + pv0];
            r1 = reinterpret_cast<const float4*>(dptr + (size_t)d1 * NPIX)[p4b + pv1];
            nlab = lptr[ntile * TILE + w * 16 + (lane & 15)];
        }

        // ---- gather current tile from buf p ----
        const float* myrow = p ? grow1 : grow0;
#pragma unroll
        for (int i = 0; i < 8; i++) {
            const int myl = __shfl_sync(0xffffffffu, labReg, 2 * i + half);
            const float v = myrow[i * (2 * QROW)];
            float* pa = accb + myl * DD;
            *pa += v;
        }

        if (!more) break;

        // ---- commit prefetched tile into buf p^1 ----
        {
            float* w0 = &s_data[p ^ 1][(pv0 * 4) * QROW + dd0];
            w0[0 * QROW] = r0.x; w0[1 * QROW] = r0.y; w0[2 * QROW] = r0.z; w0[3 * QROW] = r0.w;
            float* w1 = &s_data[p ^ 1][(pv1 * 4) * QROW + dd1];
            w1[0 * QROW] = r1.x; w1[1 * QROW] = r1.y; w1[2 * QROW] = r1.z; w1[3 * QROW] = r1.w;
        }
        labReg = nlab;
        __syncthreads();       // single barrier per tile
        p ^= 1;
        tile = ntile;
    }

    __syncthreads();
    // ---- merge 16 copies -> global ----
    for (int o = t; o < KC * DD; o += 256) {
        float s = 0.f;
#pragma unroll
        for (int c = 0; c < 16; c++) s += s_acc[c * (KC * DD) + o];
        atomicAdd(&g_sums[b * KC * DD + o], s);
    }
}

// ---------------- centers + dist + reg; zero vtot/ticket ----------------
__global__ void __launch_bounds__(256) k_centers() {
    __shared__ float s_c[BQ * KC * DD];
    __shared__ float s_ic[BQ * KC];
    __shared__ float s_red[8];
    const int t = threadIdx.x;

    if (t == 0) { g_vtot = 0.f; g_done = 0u; }

    if (t < BQ * KC) {
        const int b = t / KC, k = t - b * KC;
        int s = 0;
#pragma unroll
        for (int c = 0; c < CNT_BLKS; c++)
            s += g_cnt_part[(b * CNT_BLKS + c) * KC + k];
        const float cnt = (float)s;
        const float inv = 1.f / cnt;
        g_counts[t] = cnt;
        g_invc[t] = inv;
        s_ic[t] = inv;
    }
    __syncthreads();

    for (int i = t; i < BQ * KC * DD; i += 256) {
        const float c = g_sums[i] * s_ic[i >> 4];
        s_c[i] = c;
        g_centers[i] = c;
    }
    __syncthreads();

    const float inv_pairs = 1.f / (2.f * KC * (KC - 1));
    float acc = 0.f;
    for (int i = t; i < BQ * KC * KC; i += 256) {
        const int b = i / (KC * KC);
        const int r = i - b * KC * KC;
        const int k1 = r / KC, k2 = r - k1 * KC;
        const float* c1 = &s_c[(b * KC + k1) * DD];
        const float* c2 = &s_c[(b * KC + k2) * DD];
        float sq = 0.f;
#pragma unroll
        for (int d = 0; d < DD; d++) { const float df = c1[d] - c2[d]; sq += df * df; }
        const float cd = (k1 == k2) ? 0.f : sqrtf(sq);
        const float h  = fmaxf(2.f - cd, 0.f);
        acc += h * h * inv_pairs;
    }
    for (int i = t; i < BQ * KC; i += 256) {
        const float* c = &s_c[i * DD];
        float sq = 0.f;
#pragma unroll
        for (int d = 0; d < DD; d++) sq += c[d] * c[d];
        acc += sqrtf(sq) * (1.f / KC);
    }

#pragma unroll
    for (int o = 16; o > 0; o >>= 1)
        acc += __shfl_xor_sync(0xffffffffu, acc, o);
    if ((t & 31) == 0) s_red[t >> 5] = acc;
    __syncthreads();
    if (t < 8) {
        float v = s_red[t];
#pragma unroll
        for (int o = 4; o > 0; o >>= 1)
            v += __shfl_xor_sync(0xffu, v, o);
        if (t == 0) g_extra = v;
    }
}

// ---------------- pass 2: hinged variance, merged 8-point body -------------
__global__ void __launch_bounds__(256, 4) k_var(const float* __restrict__ data,
                                                const int*  __restrict__ labels,
                                                float* __restrict__ out,
                                                int nblocks) {
    __shared__ float s_c[KC * KP];
    __shared__ float s_ic[KC];
    __shared__ float s_red[8];
    __shared__ bool s_last;
    const int t = threadIdx.x;
    const int b = blockIdx.y;

    for (int i = t; i < KC * DD; i += 256)
        s_c[(i >> 4) * KP + (i & 15)] = g_centers[b * KC * DD + i];
    if (t < KC) s_ic[t] = g_invc[b * KC + t];
    __syncthreads();

    const float* dptr = data + (size_t)b * DD * NPIX;
    const int*   lptr = labels + (size_t)b * NPIX;

    const int bx = gridDim.x - 1 - blockIdx.x;   // reversed: L2 reuse from pass 1
    const int vn0 = bx * 512 + t;
    const int vn1 = vn0 + 256;

    const int4 la = reinterpret_cast<const int4*>(lptr)[vn0];
    const int4 lb = reinterpret_cast<const int4*>(lptr)[vn1];
    const int oa0 = la.x * KP, oa1 = la.y * KP, oa2 = la.z * KP, oa3 = la.w * KP;
    const int ob0 = lb.x * KP, ob1 = lb.y * KP, ob2 = lb.z * KP, ob3 = lb.w * KP;

    float sa0 = 0.f, sa1 = 0.f, sa2 = 0.f, sa3 = 0.f;
    float sb0 = 0.f, sb1 = 0.f, sb2 = 0.f, sb3 = 0.f;
#pragma unroll
    for (int d = 0; d < DD; d++) {
        const float4 va = reinterpret_cast<const float4*>(dptr + (size_t)d * NPIX)[vn0];
        const float4 vb = reinterpret_cast<const float4*>(dptr + (size_t)d * NPIX)[vn1];
        const float a0 = va.x - s_c[oa0 + d]; sa0 += a0 * a0;
        const float a1 = va.y - s_c[oa1 + d]; sa1 += a1 * a1;
        const float a2 = va.z - s_c[oa2 + d]; sa2 += a2 * a2;
        const float a3 = va.w - s_c[oa3 + d]; sa3 += a3 * a3;
        const float b0 = vb.x - s_c[ob0 + d]; sb0 += b0 * b0;
        const float b1 = vb.y - s_c[ob1 + d]; sb1 += b1 * b1;
        const float b2 = vb.z - s_c[ob2 + d]; sb2 += b2 * b2;
        const float b3 = vb.w - s_c[ob3 + d]; sb3 += b3 * b3;
    }
    const float h0 = fmaxf(sqrtf(sa0) - 1.f, 0.f);
    const float h1 = fmaxf(sqrtf(sa1) - 1.f, 0.f);
    const float h2 = fmaxf(sqrtf(sa2) - 1.f, 0.f);
    const float h3 = fmaxf(sqrtf(sa3) - 1.f, 0.f);
    const float h4 = fmaxf(sqrtf(sb0) - 1.f, 0.f);
    const float h5 = fmaxf(sqrtf(sb1) - 1.f, 0.f);
    const float h6 = fmaxf(sqrtf(sb2) - 1.f, 0.f);
    const float h7 = fmaxf(sqrtf(sb3) - 1.f, 0.f);
    float acc = h0 * h0 * s_ic[la.x] + h1 * h1 * s_ic[la.y]
              + h2 * h2 * s_ic[la.z] + h3 * h3 * s_ic[la.w]
              + h4 * h4 * s_ic[lb.x] + h5 * h5 * s_ic[lb.y]
              + h6 * h6 * s_ic[lb.z] + h7 * h7 * s_ic[lb.w];

#pragma unroll
    for (int o = 16; o > 0; o >>= 1)
        acc += __shfl_xor_sync(0xffffffffu, acc, o);
    if ((t & 31) == 0) s_red[t >> 5] = acc;
    __syncthreads();
    if (t < 8) {
        float v = s_red[t];
#pragma unroll
        for (int o = 4; o > 0; o >>= 1)
            v += __shfl_xor_sync(0xffu, v, o);
        if (t == 0) {
            atomicAdd(&g_vtot, v);
            __threadfence();
            const unsigned ticket = atomicAdd(&g_done, 1u);
            s_last = (ticket == (unsigned)(nblocks - 1));
        }
    }
    __syncthreads();
    if (s_last && t == 0) {
        const float vt = *(volatile float*)&g_vtot;
        out[0] = (vt + g_extra) * (1.f / BQ);
    }
}

// ---------------- entry point ----------------
extern "C" void kernel_launch(void* const* d_in, const int* in_sizes, int n_in,
                              void* d_out, int out_size) {
    const float* data   = (const float*)d_in[0];
    const int*   labels = (const int*)d_in[1];
    float* out = (float*)d_out;

    dim3 cgrid(CNT_BLKS, BQ);
    k_count<<<cgrid, 256>>>(labels);

    dim3 agrid(ABLK_X, BQ);
    k_accum<<<agrid, 256>>>(data, labels);

    k_centers<<<1, 256>>>();

    dim3 vgrid(NPIX / 2048, BQ);
    k_var<<<vgrid, 256>>>(data, labels, out, (NPIX / 2048) * BQ);
}